// round 5
// baseline (speedup 1.0000x reference)
#include <cuda_runtime.h>
#include <cuda_bf16.h>

#define NN       8192
#define EE       262144
#define IN_NODE  11
#define H_NF     4
#define OUT_NF   4
#define EMB_NF   2
#define TILE     64
#define NT       (NN / TILE)          // 128 tile rows
#define NBLOCKS  (NT * (NT + 1) / 2)  // 8256 upper-tri decode tiles

#define INIT_B   32                    // init blocks (8192 nodes / 256)
#define SCAT_B   1024                  // scatter blocks (262144 edges / 256)
#define ENC_B    (INIT_B + SCAT_B)     // 1056
#define GRID_B   (ENC_B + NBLOCKS)     // 9312 total blocks

// Scratch + gates (static device globals; gates reset by last block each call)
__device__ __align__(16) float g_emb[NN * EMB_NF];
__device__ volatile int g_gate1;   // init complete
__device__ volatile int g_gate2;   // scatter complete
__device__ int          g_fin;     // finish counter (for gate reset)

// ---------------------------------------------------------------------------
// Fold helper: T = W2 @ We  (4x2). ~32 FMA; computed locally where needed.
// ---------------------------------------------------------------------------
__device__ __forceinline__ void fold_T(const float* __restrict__ W2,
                                       const float* __restrict__ We,
                                       float T[H_NF][EMB_NF]) {
#pragma unroll
    for (int h = 0; h < H_NF; h++)
#pragma unroll
        for (int j = 0; j < EMB_NF; j++) {
            float s = 0.0f;
#pragma unroll
            for (int o = 0; o < OUT_NF; o++)
                s = fmaf(__ldg(&W2[h * OUT_NF + o]), __ldg(&We[o * EMB_NF + j]), s);
            T[h][j] = s;
        }
}

__device__ __forceinline__ float sig_pair(float2 ei, float ex, float ey) {
    float dx = ei.x - ex;
    float dy = ei.y - ey;
    float d  = fmaf(dx, dx, dy * dy);
    float t  = fmaf(10.0f, d, -1.0f);
    return __fdividef(1.0f, 1.0f + __expf(-t));
}

__device__ __forceinline__ void spin_gate(volatile int* gate, int target) {
    if (threadIdx.x == 0) {
        while (*gate != target) __nanosleep(64);
    }
    __syncthreads();
    __threadfence();   // acquire: order gate observation before data reads
}

// ---------------------------------------------------------------------------
// Megakernel: init -> (gate1) -> scatter -> (gate2) -> decode, one launch.
// ---------------------------------------------------------------------------
__global__ void __launch_bounds__(256) k_all(
        const int* __restrict__ eidx, const float* __restrict__ eattr,
        const float* __restrict__ nf,
        const float* __restrict__ W1, const float* __restrict__ b1,
        const float* __restrict__ W2, const float* __restrict__ b2,
        const float* __restrict__ We, const float* __restrict__ be,
        float* __restrict__ out, float* __restrict__ out_emb) {
    __shared__ float sm[TILE][TILE + 1];
    int b = blockIdx.x;

    if (b < INIT_B) {
        // ---- phase 0: base embedding, sole writer, plain stores ----
        float T[H_NF][EMB_NF];
        fold_T(W2, We, T);
        int i = b * 256 + threadIdx.x;
        float c0 = __ldg(&be[0]), c1 = __ldg(&be[1]);
#pragma unroll
        for (int h = 0; h < H_NF; h++) {
            float bh = __ldg(&b1[h]);
            c0 = fmaf(bh, T[h][0], c0);
            c1 = fmaf(bh, T[h][1], c1);
        }
#pragma unroll
        for (int o = 0; o < OUT_NF; o++) {
            float bo = __ldg(&b2[o]);
            c0 = fmaf(bo, __ldg(&We[o * EMB_NF + 0]), c0);
            c1 = fmaf(bo, __ldg(&We[o * EMB_NF + 1]), c1);
        }
#pragma unroll
        for (int k = 0; k < IN_NODE; k++) {
            float x = __ldg(&nf[i * IN_NODE + k]);
            float m0 = 0.0f, m1 = 0.0f;
#pragma unroll
            for (int h = 0; h < H_NF; h++) {
                float w = __ldg(&W1[k * H_NF + h]);
                m0 = fmaf(w, T[h][0], m0);
                m1 = fmaf(w, T[h][1], m1);
            }
            c0 = fmaf(x, m0, c0);
            c1 = fmaf(x, m1, c1);
        }
        g_emb[i * 2 + 0] = c0;
        g_emb[i * 2 + 1] = c1;
        __syncthreads();
        if (threadIdx.x == 0) {
            __threadfence();                       // release stores
            atomicAdd((int*)&g_gate1, 1);
        }
    } else if (b < ENC_B) {
        // ---- phase 1: edge scatter (atomicAdd on top of base emb) ----
        float T[H_NF][EMB_NF];
        fold_T(W2, We, T);
        int e = (b - INIT_B) * 256 + threadIdx.x;
        float4 a = __ldg(reinterpret_cast<const float4*>(&eattr[e * 4]));
        float av[4] = {a.x, a.y, a.z, a.w};
        int r = __ldg(&eidx[e]);

        spin_gate(&g_gate1, INIT_B);

        float c0 = 0.0f, c1 = 0.0f;
#pragma unroll
        for (int k = 0; k < 4; k++) {
            float m0 = 0.0f, m1 = 0.0f;
#pragma unroll
            for (int h = 0; h < H_NF; h++) {
                float w = __ldg(&W1[(IN_NODE + k) * H_NF + h]);
                m0 = fmaf(w, T[h][0], m0);
                m1 = fmaf(w, T[h][1], m1);
            }
            c0 = fmaf(av[k], m0, c0);
            c1 = fmaf(av[k], m1, c1);
        }
        atomicAdd(&g_emb[r * 2 + 0], c0);
        atomicAdd(&g_emb[r * 2 + 1], c1);
        __syncthreads();
        if (threadIdx.x == 0) {
            __threadfence();                       // release atomics
            atomicAdd((int*)&g_gate2, 1);
        }
    } else {
        // ---- phase 2: symmetric tiled decode ----
        spin_gate(&g_gate2, SCAT_B);

        int db = b - ENC_B;
        // first 16 decode blocks emit node_emb tail (16*256 float4 = 16384 f)
        if (db < 16) {
            int t = db * 256 + threadIdx.x;
            reinterpret_cast<float4*>(out_emb)[t] =
                reinterpret_cast<const float4*>(g_emb)[t];
        }

        // map linear index -> upper-triangular tile (I, J)
        float bf = (float)db;
        const float tnp1 = 2.0f * NT + 1.0f;   // 257
        int I = (int)(0.5f * (tnp1 - sqrtf(tnp1 * tnp1 - 8.0f * bf)));
        if (I < 0) I = 0;
        if (I > NT - 1) I = NT - 1;
        while ((I + 1) * NT - (I + 1) * I / 2 <= db) I++;
        while (I * NT - I * (I - 1) / 2 > db) I--;
        int J = I + (db - (I * NT - I * (I - 1) / 2));
        bool diag = (I == J);

        int i0 = I * TILE, j0 = J * TILE;
        int tj = threadIdx.x & 15;
        int ti = threadIdx.x >> 4;
        int jb = tj * 4;

        const float* eJ = &g_emb[(j0 + jb) * 2];
        float4 ea = *reinterpret_cast<const float4*>(eJ);
        float4 eb = *reinterpret_cast<const float4*>(eJ + 4);

#pragma unroll
        for (int p = 0; p < 4; p++) {
            int il = ti + p * 16;
            float2 ei = *reinterpret_cast<const float2*>(&g_emb[(i0 + il) * 2]);
            float4 r;
            r.x = sig_pair(ei, ea.x, ea.y);
            r.y = sig_pair(ei, ea.z, ea.w);
            r.z = sig_pair(ei, eb.x, eb.y);
            r.w = sig_pair(ei, eb.z, eb.w);
            if (diag) {
                unsigned k = (unsigned)il - (unsigned)jb;
                if (k < 4u) {
                    if (k == 0u)      r.x = 0.0f;
                    else if (k == 1u) r.y = 0.0f;
                    else if (k == 2u) r.z = 0.0f;
                    else              r.w = 0.0f;
                }
            }
            __stcs(reinterpret_cast<float4*>(&out[(size_t)(i0 + il) * NN + j0 + jb]), r);
            if (!diag) {
                sm[jb + 0][il] = r.x;
                sm[jb + 1][il] = r.y;
                sm[jb + 2][il] = r.z;
                sm[jb + 3][il] = r.w;
            }
        }

        if (!diag) {
            __syncthreads();
#pragma unroll
            for (int p = 0; p < 4; p++) {
                int jr = ti + p * 16;
                int ib = tj * 4;
                float4 w;
                w.x = sm[jr][ib + 0];
                w.y = sm[jr][ib + 1];
                w.z = sm[jr][ib + 2];
                w.w = sm[jr][ib + 3];
                __stcs(reinterpret_cast<float4*>(&out[(size_t)(j0 + jr) * NN + i0 + ib]), w);
            }
        }
    }

    // ---- epilogue: last block of the whole grid resets the gates ----
    __syncthreads();
    if (threadIdx.x == 0) {
        int v = atomicAdd(&g_fin, 1);
        if (v == GRID_B - 1) {
            g_gate1 = 0;
            g_gate2 = 0;
            g_fin   = 0;
            __threadfence();
        }
    }
}

// ---------------------------------------------------------------------------
// launch
// ---------------------------------------------------------------------------
extern "C" void kernel_launch(void* const* d_in, const int* in_sizes, int n_in,
                              void* d_out, int out_size) {
    const float* node_feats = (const float*)d_in[0];
    const int*   edge_index = (const int*)d_in[1];
    const float* edge_attr  = (const float*)d_in[2];
    const float* W1 = (const float*)d_in[3];
    const float* b1 = (const float*)d_in[4];
    const float* W2 = (const float*)d_in[5];
    const float* b2 = (const float*)d_in[6];
    const float* We = (const float*)d_in[7];
    const float* be = (const float*)d_in[8];

    float* out = (float*)d_out;
    float* out_emb = out + (size_t)NN * NN;   // adj [N*N] then node_emb [N*2]

    k_all<<<GRID_B, 256>>>(edge_index, edge_attr, node_feats,
                           W1, b1, W2, b2, We, be, out, out_emb);
}

// round 8
// speedup vs baseline: 1.1084x; 1.1084x over previous
#include <cuda_runtime.h>
#include <cuda_bf16.h>

#define NN       8192
#define EE       262144
#define IN_NODE  11
#define H_NF     4
#define OUT_NF   4
#define EMB_NF   2
#define TILE     64
#define NT       (NN / TILE)          // 128 tile rows
#define NBLOCKS  (NT * (NT + 1) / 2)  // 8256 upper-tri decode tiles

#define SCAT_BLK (EE / 256)           // 1024 scatter blocks
#define INIT_BLK (NN / 256)           // 32 init blocks

// Scratch (static device globals — zero-initialized at module load;
// k_decode restores the zero state at the end of every call, so k_fused
// always observes g_emb == 0 on entry, including across graph replays).
__device__ __align__(16) float g_emb[NN * EMB_NF];
__device__ int g_fin;

// ---------------------------------------------------------------------------
// Fold helper: T = W2 @ We  (4x2). ~32 FMA; every thread computes it locally.
// ---------------------------------------------------------------------------
__device__ __forceinline__ void fold_T(const float* __restrict__ W2,
                                       const float* __restrict__ We,
                                       float T[H_NF][EMB_NF]) {
#pragma unroll
    for (int h = 0; h < H_NF; h++)
#pragma unroll
        for (int j = 0; j < EMB_NF; j++) {
            float s = 0.0f;
#pragma unroll
            for (int o = 0; o < OUT_NF; o++)
                s = fmaf(__ldg(&W2[h * OUT_NF + o]), __ldg(&We[o * EMB_NF + j]), s);
            T[h][j] = s;
        }
}

// ---------------------------------------------------------------------------
// k1 (fused): blocks [0, SCAT_BLK) scatter edge contributions,
//             blocks [SCAT_BLK, SCAT_BLK+INIT_BLK) add per-node base emb.
// Both paths atomicAdd into g_emb (== 0 on entry) -> no ordering needed.
// ---------------------------------------------------------------------------
__global__ void __launch_bounds__(256) k_fused(
        const int* __restrict__ eidx, const float* __restrict__ eattr,
        const float* __restrict__ nf,
        const float* __restrict__ W1, const float* __restrict__ b1,
        const float* __restrict__ W2, const float* __restrict__ b2,
        const float* __restrict__ We, const float* __restrict__ be) {
    int b = blockIdx.x;
    float T[H_NF][EMB_NF];
    fold_T(W2, We, T);

    if (b < SCAT_BLK) {
        // --- edge scatter: emb[row[e]] += edge_attr[e] @ (W1[11:15] W2 We) ---
        int e = b * 256 + threadIdx.x;
        float4 a = __ldg(reinterpret_cast<const float4*>(&eattr[e * 4]));
        float av[4] = {a.x, a.y, a.z, a.w};
        float c0 = 0.0f, c1 = 0.0f;
#pragma unroll
        for (int k = 0; k < 4; k++) {
            float m0 = 0.0f, m1 = 0.0f;
#pragma unroll
            for (int h = 0; h < H_NF; h++) {
                float w = __ldg(&W1[(IN_NODE + k) * H_NF + h]);
                m0 = fmaf(w, T[h][0], m0);
                m1 = fmaf(w, T[h][1], m1);
            }
            c0 = fmaf(av[k], m0, c0);
            c1 = fmaf(av[k], m1, c1);
        }
        int r = __ldg(&eidx[e]);
        atomicAdd(&g_emb[r * 2 + 0], c0);
        atomicAdd(&g_emb[r * 2 + 1], c1);
    } else {
        // --- base emb: bias chain + node_feats_i @ (W1[0:11] W2 We) ---
        int i = (b - SCAT_BLK) * 256 + threadIdx.x;
        float c0 = __ldg(&be[0]), c1 = __ldg(&be[1]);
#pragma unroll
        for (int h = 0; h < H_NF; h++) {
            float bh = __ldg(&b1[h]);
            c0 = fmaf(bh, T[h][0], c0);
            c1 = fmaf(bh, T[h][1], c1);
        }
#pragma unroll
        for (int o = 0; o < OUT_NF; o++) {
            float bo = __ldg(&b2[o]);
            c0 = fmaf(bo, __ldg(&We[o * EMB_NF + 0]), c0);
            c1 = fmaf(bo, __ldg(&We[o * EMB_NF + 1]), c1);
        }
#pragma unroll
        for (int k = 0; k < IN_NODE; k++) {
            float x = __ldg(&nf[i * IN_NODE + k]);
            float m0 = 0.0f, m1 = 0.0f;
#pragma unroll
            for (int h = 0; h < H_NF; h++) {
                float w = __ldg(&W1[k * H_NF + h]);
                m0 = fmaf(w, T[h][0], m0);
                m1 = fmaf(w, T[h][1], m1);
            }
            c0 = fmaf(x, m0, c0);
            c1 = fmaf(x, m1, c1);
        }
        atomicAdd(&g_emb[i * 2 + 0], c0);
        atomicAdd(&g_emb[i * 2 + 1], c1);
    }
}

// ---------------------------------------------------------------------------
// k2: symmetric tiled decode + zero-restore epilogue.
// Block b -> upper-tri tile (I,J), J >= I. Computes 64x64 sigmoid tile once,
// stores it direct (coalesced float4 streaming) and, for off-diagonal tiles,
// stores the transpose via smem (also coalesced). Halves the MUFU work.
// Blocks 0..15 additionally emit node_emb to the output tail.
// The LAST finishing block re-zeros g_emb (all reads are done by then),
// restoring the invariant k_fused relies on for the next call.
// ---------------------------------------------------------------------------
__device__ __forceinline__ float sig_pair(float2 ei, float ex, float ey) {
    float dx = ei.x - ex;
    float dy = ei.y - ey;
    float d  = fmaf(dx, dx, dy * dy);
    float t  = fmaf(10.0f, d, -1.0f);
    return __fdividef(1.0f, 1.0f + __expf(-t));
}

__global__ void __launch_bounds__(256) k_decode(float* __restrict__ out,
                                                float* __restrict__ out_emb) {
    __shared__ float sm[TILE][TILE + 1];
    __shared__ int s_last;
    int b = blockIdx.x;

    // emit node_emb (16 blocks x 256 threads x 1 float4 = 16384 floats)
    if (b < 16) {
        int t = b * 256 + threadIdx.x;
        reinterpret_cast<float4*>(out_emb)[t] =
            reinterpret_cast<const float4*>(g_emb)[t];
    }

    // map linear block index -> upper-triangular tile (I, J)
    float bf = (float)b;
    const float tnp1 = 2.0f * NT + 1.0f;   // 257
    int I = (int)(0.5f * (tnp1 - sqrtf(tnp1 * tnp1 - 8.0f * bf)));
    if (I < 0) I = 0;
    if (I > NT - 1) I = NT - 1;
    while ((I + 1) * NT - (I + 1) * I / 2 <= b) I++;   // off(I+1) <= b
    while (I * NT - I * (I - 1) / 2 > b) I--;          // off(I)   >  b
    int J = I + (b - (I * NT - I * (I - 1) / 2));
    bool diag = (I == J);

    int i0 = I * TILE, j0 = J * TILE;
    int tj = threadIdx.x & 15;   // 0..15 (4 j's each)
    int ti = threadIdx.x >> 4;   // 0..15 row group
    int jb = tj * 4;

    // this thread's 4 j-embeddings (fixed across passes)
    const float* eJ = &g_emb[(j0 + jb) * 2];
    float4 ea = *reinterpret_cast<const float4*>(eJ);       // j, j+1
    float4 eb = *reinterpret_cast<const float4*>(eJ + 4);   // j+2, j+3

#pragma unroll
    for (int p = 0; p < 4; p++) {
        int il = ti + p * 16;
        float2 ei = *reinterpret_cast<const float2*>(&g_emb[(i0 + il) * 2]);
        float4 r;
        r.x = sig_pair(ei, ea.x, ea.y);
        r.y = sig_pair(ei, ea.z, ea.w);
        r.z = sig_pair(ei, eb.x, eb.y);
        r.w = sig_pair(ei, eb.z, eb.w);
        if (diag) {
            unsigned k = (unsigned)il - (unsigned)jb;
            if (k < 4u) {
                if (k == 0u)      r.x = 0.0f;
                else if (k == 1u) r.y = 0.0f;
                else if (k == 2u) r.z = 0.0f;
                else              r.w = 0.0f;
            }
        }
        __stcs(reinterpret_cast<float4*>(&out[(size_t)(i0 + il) * NN + j0 + jb]), r);
        if (!diag) {
            sm[jb + 0][il] = r.x;
            sm[jb + 1][il] = r.y;
            sm[jb + 2][il] = r.z;
            sm[jb + 3][il] = r.w;
        }
    }

    if (!diag) {
        __syncthreads();
#pragma unroll
        for (int p = 0; p < 4; p++) {
            int jr = ti + p * 16;
            int ib = tj * 4;
            float4 w;
            w.x = sm[jr][ib + 0];
            w.y = sm[jr][ib + 1];
            w.z = sm[jr][ib + 2];
            w.w = sm[jr][ib + 3];
            __stcs(reinterpret_cast<float4*>(&out[(size_t)(j0 + jr) * NN + i0 + ib]), w);
        }
    }

    // ---- epilogue: last finishing block restores g_emb = 0 and g_fin = 0 ----
    __syncthreads();
    if (threadIdx.x == 0) {
        __threadfence();
        s_last = (atomicAdd(&g_fin, 1) == NBLOCKS - 1) ? 1 : 0;
    }
    __syncthreads();
    if (s_last) {
        // all NBLOCKS blocks have finished -> every g_emb read is complete
        float4 z = make_float4(0.f, 0.f, 0.f, 0.f);
#pragma unroll
        for (int p = 0; p < NN * EMB_NF / 4 / 256; p++)       // 16 float4/thread
            reinterpret_cast<float4*>(g_emb)[p * 256 + threadIdx.x] = z;
        if (threadIdx.x == 0) g_fin = 0;
    }
}

// ---------------------------------------------------------------------------
// launch
// ---------------------------------------------------------------------------
extern "C" void kernel_launch(void* const* d_in, const int* in_sizes, int n_in,
                              void* d_out, int out_size) {
    const float* node_feats = (const float*)d_in[0];
    const int*   edge_index = (const int*)d_in[1];
    const float* edge_attr  = (const float*)d_in[2];
    const float* W1 = (const float*)d_in[3];
    const float* b1 = (const float*)d_in[4];
    const float* W2 = (const float*)d_in[5];
    const float* b2 = (const float*)d_in[6];
    const float* We = (const float*)d_in[7];
    const float* be = (const float*)d_in[8];

    float* out = (float*)d_out;
    float* out_emb = out + (size_t)NN * NN;   // adj [N*N] then node_emb [N*2]

    k_fused<<<SCAT_BLK + INIT_BLK, 256>>>(edge_index, edge_attr, node_feats,
                                          W1, b1, W2, b2, We, be);
    k_decode<<<NBLOCKS, 256>>>(out, out_emb);
}

// round 10
// speedup vs baseline: 1.1434x; 1.0315x over previous
#include <cuda_runtime.h>
#include <cuda_bf16.h>

#define NN       8192
#define EE       262144
#define IN_NODE  11
#define H_NF     4
#define OUT_NF   4
#define EMB_NF   2

#define ROWS_PER_BLK 2
#define DEC_BLOCKS   (NN / ROWS_PER_BLK)     // 4096 decode blocks
#define CHUNKS       (NN / 4 / 256)          // 8 float4-chunks per row per thread

#define SCAT_BLK 256                          // 256 blocks x 256 thr x 4 edges
#define INIT_BLK 8                            // 8 blocks x 256 thr x 4 nodes

// Scratch (static device globals — zero-initialized at module load;
// k_decode restores g_emb = 0 at the end of every call, so k_fused always
// observes zeros on entry, including across graph replays).
__device__ __align__(16) float g_emb[NN * EMB_NF];
__device__ int g_fin;

// ---------------------------------------------------------------------------
// Fold helper: T = W2 @ We  (4x2). ~32 FMA; computed locally where needed.
// ---------------------------------------------------------------------------
__device__ __forceinline__ void fold_T(const float* __restrict__ W2,
                                       const float* __restrict__ We,
                                       float T[H_NF][EMB_NF]) {
#pragma unroll
    for (int h = 0; h < H_NF; h++)
#pragma unroll
        for (int j = 0; j < EMB_NF; j++) {
            float s = 0.0f;
#pragma unroll
            for (int o = 0; o < OUT_NF; o++)
                s = fmaf(__ldg(&W2[h * OUT_NF + o]), __ldg(&We[o * EMB_NF + j]), s);
            T[h][j] = s;
        }
}

// ---------------------------------------------------------------------------
// k1 (fused): blocks [0, SCAT_BLK) scatter 4 edges/thread,
//             blocks [SCAT_BLK, SCAT_BLK+INIT_BLK) add base emb, 4 nodes/thread.
// Both paths atomicAdd into g_emb (== 0 on entry) -> order-free.
// ---------------------------------------------------------------------------
__global__ void __launch_bounds__(256) k_fused(
        const int* __restrict__ eidx, const float* __restrict__ eattr,
        const float* __restrict__ nf,
        const float* __restrict__ W1, const float* __restrict__ b1,
        const float* __restrict__ W2, const float* __restrict__ b2,
        const float* __restrict__ We, const float* __restrict__ be) {
    int b = blockIdx.x;
    float T[H_NF][EMB_NF];
    fold_T(W2, We, T);

    if (b < SCAT_BLK) {
        // --- edge scatter: emb[row[e]] += edge_attr[e] @ (W1[11:15] W2 We) ---
        // Pre-fold the 4x2 edge projection P = W1[11:15] @ T (8 regs).
        float P[4][2];
#pragma unroll
        for (int k = 0; k < 4; k++)
#pragma unroll
            for (int j = 0; j < 2; j++) {
                float s = 0.0f;
#pragma unroll
                for (int h = 0; h < H_NF; h++)
                    s = fmaf(__ldg(&W1[(IN_NODE + k) * H_NF + h]), T[h][j], s);
                P[k][j] = s;
            }
        int g = b * 256 + threadIdx.x;           // 65536 threads
#pragma unroll
        for (int k4 = 0; k4 < 4; k4++) {
            int e = g + k4 * 65536;
            float4 a = __ldg(reinterpret_cast<const float4*>(&eattr[e * 4]));
            float c0 = a.x * P[0][0];
            float c1 = a.x * P[0][1];
            c0 = fmaf(a.y, P[1][0], c0); c1 = fmaf(a.y, P[1][1], c1);
            c0 = fmaf(a.z, P[2][0], c0); c1 = fmaf(a.z, P[2][1], c1);
            c0 = fmaf(a.w, P[3][0], c0); c1 = fmaf(a.w, P[3][1], c1);
            int r = __ldg(&eidx[e]);
            atomicAdd(&g_emb[r * 2 + 0], c0);
            atomicAdd(&g_emb[r * 2 + 1], c1);
        }
    } else {
        // --- base emb: bias chain + node_feats_i @ (W1[0:11] W2 We) ---
        float cb0 = __ldg(&be[0]), cb1 = __ldg(&be[1]);
#pragma unroll
        for (int h = 0; h < H_NF; h++) {
            float bh = __ldg(&b1[h]);
            cb0 = fmaf(bh, T[h][0], cb0);
            cb1 = fmaf(bh, T[h][1], cb1);
        }
#pragma unroll
        for (int o = 0; o < OUT_NF; o++) {
            float bo = __ldg(&b2[o]);
            cb0 = fmaf(bo, __ldg(&We[o * EMB_NF + 0]), cb0);
            cb1 = fmaf(bo, __ldg(&We[o * EMB_NF + 1]), cb1);
        }
        // node-feature projection M = W1[0:11] @ T (22 regs)
        float M[IN_NODE][2];
#pragma unroll
        for (int k = 0; k < IN_NODE; k++)
#pragma unroll
            for (int j = 0; j < 2; j++) {
                float s = 0.0f;
#pragma unroll
                for (int h = 0; h < H_NF; h++)
                    s = fmaf(__ldg(&W1[k * H_NF + h]), T[h][j], s);
                M[k][j] = s;
            }
        int g = (b - SCAT_BLK) * 256 + threadIdx.x;   // 2048 threads
#pragma unroll
        for (int k4 = 0; k4 < 4; k4++) {
            int i = g + k4 * 2048;
            float c0 = cb0, c1 = cb1;
#pragma unroll
            for (int k = 0; k < IN_NODE; k++) {
                float x = __ldg(&nf[i * IN_NODE + k]);
                c0 = fmaf(x, M[k][0], c0);
                c1 = fmaf(x, M[k][1], c1);
            }
            atomicAdd(&g_emb[i * 2 + 0], c0);
            atomicAdd(&g_emb[i * 2 + 1], c1);
        }
    }
}

// ---------------------------------------------------------------------------
// k2: dense decode. Block b owns output rows 2b and 2b+1 (2 x 32KB contiguous
// streams -> maximally DRAM-friendly writes). No smem, no syncthreads.
// g_emb (64KB) is L1-resident per SM after the first block.
// Blocks 0..15 also emit the node_emb tail. Last finishing block re-zeros
// g_emb (all reads complete by then) to restore k_fused's invariant.
// ---------------------------------------------------------------------------
__device__ __forceinline__ float sig_pair(float2 ei, float ex, float ey) {
    float dx = ei.x - ex;
    float dy = ei.y - ey;
    float d  = fmaf(dx, dx, dy * dy);
    float t  = fmaf(10.0f, d, -1.0f);
    return __fdividef(1.0f, 1.0f + __expf(-t));
}

__global__ void __launch_bounds__(256) k_decode(float* __restrict__ out,
                                                float* __restrict__ out_emb) {
    __shared__ int s_last;
    int b = blockIdx.x;

    // node_emb tail: 16 blocks x 256 threads x 1 float4 = 16384 floats
    if (b < 16) {
        int t = b * 256 + threadIdx.x;
        reinterpret_cast<float4*>(out_emb)[t] =
            reinterpret_cast<const float4*>(g_emb)[t];
    }

    int i0 = b * ROWS_PER_BLK;
    float2 e0 = *reinterpret_cast<const float2*>(&g_emb[i0 * 2]);
    float2 e1 = *reinterpret_cast<const float2*>(&g_emb[(i0 + 1) * 2]);
    float* row0 = &out[(size_t)i0 * NN];
    float* row1 = row0 + NN;

#pragma unroll
    for (int p = 0; p < CHUNKS; p++) {
        int c  = p * 256 + threadIdx.x;        // float4 index in row, 0..2047
        int jb = c * 4;
        float4 ja = *reinterpret_cast<const float4*>(&g_emb[jb * 2]);      // j,j+1
        float4 jc = *reinterpret_cast<const float4*>(&g_emb[jb * 2 + 4]);  // j+2,j+3

        float4 r0, r1;
        r0.x = sig_pair(e0, ja.x, ja.y);  r1.x = sig_pair(e1, ja.x, ja.y);
        r0.y = sig_pair(e0, ja.z, ja.w);  r1.y = sig_pair(e1, ja.z, ja.w);
        r0.z = sig_pair(e0, jc.x, jc.y);  r1.z = sig_pair(e1, jc.x, jc.y);
        r0.w = sig_pair(e0, jc.z, jc.w);  r1.w = sig_pair(e1, jc.z, jc.w);

        unsigned k0 = (unsigned)i0 - (unsigned)jb;          // diag row i0
        if (k0 < 4u) {
            if (k0 == 0u)      r0.x = 0.0f;
            else if (k0 == 1u) r0.y = 0.0f;
            else if (k0 == 2u) r0.z = 0.0f;
            else               r0.w = 0.0f;
        }
        unsigned k1 = (unsigned)(i0 + 1) - (unsigned)jb;    // diag row i0+1
        if (k1 < 4u) {
            if (k1 == 0u)      r1.x = 0.0f;
            else if (k1 == 1u) r1.y = 0.0f;
            else if (k1 == 2u) r1.z = 0.0f;
            else               r1.w = 0.0f;
        }

        __stcs(reinterpret_cast<float4*>(&row0[jb]), r0);
        __stcs(reinterpret_cast<float4*>(&row1[jb]), r1);
    }

    // ---- epilogue: last finishing block restores g_emb = 0, g_fin = 0 ----
    __syncthreads();
    if (threadIdx.x == 0) {
        __threadfence();
        s_last = (atomicAdd(&g_fin, 1) == DEC_BLOCKS - 1) ? 1 : 0;
    }
    __syncthreads();
    if (s_last) {
        float4 z = make_float4(0.f, 0.f, 0.f, 0.f);
#pragma unroll
        for (int p = 0; p < NN * EMB_NF / 4 / 256; p++)     // 16 float4/thread
            reinterpret_cast<float4*>(g_emb)[p * 256 + threadIdx.x] = z;
        if (threadIdx.x == 0) g_fin = 0;
    }
}

// ---------------------------------------------------------------------------
// launch
// ---------------------------------------------------------------------------
extern "C" void kernel_launch(void* const* d_in, const int* in_sizes, int n_in,
                              void* d_out, int out_size) {
    const float* node_feats = (const float*)d_in[0];
    const int*   edge_index = (const int*)d_in[1];
    const float* edge_attr  = (const float*)d_in[2];
    const float* W1 = (const float*)d_in[3];
    const float* b1 = (const float*)d_in[4];
    const float* W2 = (const float*)d_in[5];
    const float* b2 = (const float*)d_in[6];
    const float* We = (const float*)d_in[7];
    const float* be = (const float*)d_in[8];

    float* out = (float*)d_out;
    float* out_emb = out + (size_t)NN * NN;   // adj [N*N] then node_emb [N*2]

    k_fused<<<SCAT_BLK + INIT_BLK, 256>>>(edge_index, edge_attr, node_feats,
                                          W1, b1, W2, b2, We, be);
    k_decode<<<DEC_BLOCKS, 256>>>(out, out_emb);
}

// round 11
// speedup vs baseline: 1.1998x; 1.0493x over previous
#include <cuda_runtime.h>
#include <cuda_bf16.h>

#define NN       8192
#define EE       262144
#define IN_NODE  11
#define H_NF     4
#define OUT_NF   4
#define EMB_NF   2

#define ROWS_PER_BLK 2
#define DEC_BLOCKS   (NN / ROWS_PER_BLK)     // 4096 decode blocks
#define CHUNKS       (NN / 4 / 256)          // 8 float4-chunks per row per thread

#define SCAT_BLK 256                          // 256 blocks x 256 thr x 4 edges
#define INIT_BLK 8                            // 8 blocks x 256 thr x 4 nodes

// Scratch (static device globals — zero-initialized at module load;
// k_decode restores g_emb = 0 at the end of every call, so k_fused always
// observes zeros on entry, including across graph replays).
__device__ __align__(16) float g_emb[NN * EMB_NF];
__device__ int g_fin;

// ---------------------------------------------------------------------------
// Fold helper: T = W2 @ We  (4x2). ~32 FMA; computed locally where needed.
// ---------------------------------------------------------------------------
__device__ __forceinline__ void fold_T(const float* __restrict__ W2,
                                       const float* __restrict__ We,
                                       float T[H_NF][EMB_NF]) {
#pragma unroll
    for (int h = 0; h < H_NF; h++)
#pragma unroll
        for (int j = 0; j < EMB_NF; j++) {
            float s = 0.0f;
#pragma unroll
            for (int o = 0; o < OUT_NF; o++)
                s = fmaf(__ldg(&W2[h * OUT_NF + o]), __ldg(&We[o * EMB_NF + j]), s);
            T[h][j] = s;
        }
}

// ---------------------------------------------------------------------------
// k1 (fused): blocks [0, SCAT_BLK) scatter 4 edges/thread,
//             blocks [SCAT_BLK, SCAT_BLK+INIT_BLK) add base emb, 4 nodes/thread.
// Both paths use vector float2 atomicAdd into g_emb (== 0 on entry).
// ---------------------------------------------------------------------------
__global__ void __launch_bounds__(256) k_fused(
        const int* __restrict__ eidx, const float* __restrict__ eattr,
        const float* __restrict__ nf,
        const float* __restrict__ W1, const float* __restrict__ b1,
        const float* __restrict__ W2, const float* __restrict__ b2,
        const float* __restrict__ We, const float* __restrict__ be) {
    int b = blockIdx.x;
    float T[H_NF][EMB_NF];
    fold_T(W2, We, T);

    if (b < SCAT_BLK) {
        // --- edge scatter: emb[row[e]] += edge_attr[e] @ (W1[11:15] W2 We) ---
        float P[4][2];
#pragma unroll
        for (int k = 0; k < 4; k++)
#pragma unroll
            for (int j = 0; j < 2; j++) {
                float s = 0.0f;
#pragma unroll
                for (int h = 0; h < H_NF; h++)
                    s = fmaf(__ldg(&W1[(IN_NODE + k) * H_NF + h]), T[h][j], s);
                P[k][j] = s;
            }
        int g = b * 256 + threadIdx.x;           // 65536 threads
#pragma unroll
        for (int k4 = 0; k4 < 4; k4++) {
            int e = g + k4 * 65536;
            float4 a = __ldg(reinterpret_cast<const float4*>(&eattr[e * 4]));
            float c0 = a.x * P[0][0];
            float c1 = a.x * P[0][1];
            c0 = fmaf(a.y, P[1][0], c0); c1 = fmaf(a.y, P[1][1], c1);
            c0 = fmaf(a.z, P[2][0], c0); c1 = fmaf(a.z, P[2][1], c1);
            c0 = fmaf(a.w, P[3][0], c0); c1 = fmaf(a.w, P[3][1], c1);
            int r = __ldg(&eidx[e]);
            atomicAdd(reinterpret_cast<float2*>(&g_emb[r * 2]),
                      make_float2(c0, c1));
        }
    } else {
        // --- base emb: bias chain + node_feats_i @ (W1[0:11] W2 We) ---
        float cb0 = __ldg(&be[0]), cb1 = __ldg(&be[1]);
#pragma unroll
        for (int h = 0; h < H_NF; h++) {
            float bh = __ldg(&b1[h]);
            cb0 = fmaf(bh, T[h][0], cb0);
            cb1 = fmaf(bh, T[h][1], cb1);
        }
#pragma unroll
        for (int o = 0; o < OUT_NF; o++) {
            float bo = __ldg(&b2[o]);
            cb0 = fmaf(bo, __ldg(&We[o * EMB_NF + 0]), cb0);
            cb1 = fmaf(bo, __ldg(&We[o * EMB_NF + 1]), cb1);
        }
        float M[IN_NODE][2];
#pragma unroll
        for (int k = 0; k < IN_NODE; k++)
#pragma unroll
            for (int j = 0; j < 2; j++) {
                float s = 0.0f;
#pragma unroll
                for (int h = 0; h < H_NF; h++)
                    s = fmaf(__ldg(&W1[k * H_NF + h]), T[h][j], s);
                M[k][j] = s;
            }
        int g = (b - SCAT_BLK) * 256 + threadIdx.x;   // 2048 threads
#pragma unroll
        for (int k4 = 0; k4 < 4; k4++) {
            int i = g + k4 * 2048;
            float c0 = cb0, c1 = cb1;
#pragma unroll
            for (int k = 0; k < IN_NODE; k++) {
                float x = __ldg(&nf[i * IN_NODE + k]);
                c0 = fmaf(x, M[k][0], c0);
                c1 = fmaf(x, M[k][1], c1);
            }
            atomicAdd(reinterpret_cast<float2*>(&g_emb[i * 2]),
                      make_float2(c0, c1));
        }
    }
}

// ---------------------------------------------------------------------------
// k2: dense decode. Block b owns output rows 2b and 2b+1 (2 x 32KB contiguous
// streams). Launched with PDL: grid starts while k_fused still runs; the
// cudaGridDependencySynchronize() below blocks until k_fused fully completes
// (implicit trigger at primary completion guarantees memory visibility).
// Blocks 0..15 also emit the node_emb tail. Last finishing block re-zeros
// g_emb (all reads complete by then) to restore k_fused's invariant.
// ---------------------------------------------------------------------------
__device__ __forceinline__ float sig_pair(float2 ei, float ex, float ey) {
    float dx = ei.x - ex;
    float dy = ei.y - ey;
    float d  = fmaf(dx, dx, dy * dy);
    float t  = fmaf(10.0f, d, -1.0f);
    return __fdividef(1.0f, 1.0f + __expf(-t));
}

__global__ void __launch_bounds__(256) k_decode(float* __restrict__ out,
                                                float* __restrict__ out_emb) {
    __shared__ int s_last;
    int b = blockIdx.x;
    int i0 = b * ROWS_PER_BLK;
    float* row0 = &out[(size_t)i0 * NN];
    float* row1 = row0 + NN;

    // Wait for k_fused (no-op if launched without the PDL attribute).
    cudaGridDependencySynchronize();

    // node_emb tail: 16 blocks x 256 threads x 1 float4 = 16384 floats
    if (b < 16) {
        int t = b * 256 + threadIdx.x;
        reinterpret_cast<float4*>(out_emb)[t] =
            reinterpret_cast<const float4*>(g_emb)[t];
    }

    float2 e0 = *reinterpret_cast<const float2*>(&g_emb[i0 * 2]);
    float2 e1 = *reinterpret_cast<const float2*>(&g_emb[(i0 + 1) * 2]);

#pragma unroll
    for (int p = 0; p < CHUNKS; p++) {
        int c  = p * 256 + threadIdx.x;        // float4 index in row, 0..2047
        int jb = c * 4;
        float4 ja = *reinterpret_cast<const float4*>(&g_emb[jb * 2]);      // j,j+1
        float4 jc = *reinterpret_cast<const float4*>(&g_emb[jb * 2 + 4]);  // j+2,j+3

        float4 r0, r1;
        r0.x = sig_pair(e0, ja.x, ja.y);  r1.x = sig_pair(e1, ja.x, ja.y);
        r0.y = sig_pair(e0, ja.z, ja.w);  r1.y = sig_pair(e1, ja.z, ja.w);
        r0.z = sig_pair(e0, jc.x, jc.y);  r1.z = sig_pair(e1, jc.x, jc.y);
        r0.w = sig_pair(e0, jc.z, jc.w);  r1.w = sig_pair(e1, jc.z, jc.w);

        unsigned k0 = (unsigned)i0 - (unsigned)jb;          // diag row i0
        if (k0 < 4u) {
            if (k0 == 0u)      r0.x = 0.0f;
            else if (k0 == 1u) r0.y = 0.0f;
            else if (k0 == 2u) r0.z = 0.0f;
            else               r0.w = 0.0f;
        }
        unsigned k1 = (unsigned)(i0 + 1) - (unsigned)jb;    // diag row i0+1
        if (k1 < 4u) {
            if (k1 == 0u)      r1.x = 0.0f;
            else if (k1 == 1u) r1.y = 0.0f;
            else if (k1 == 2u) r1.z = 0.0f;
            else               r1.w = 0.0f;
        }

        __stcs(reinterpret_cast<float4*>(&row0[jb]), r0);
        __stcs(reinterpret_cast<float4*>(&row1[jb]), r1);
    }

    // ---- epilogue: last finishing block restores g_emb = 0, g_fin = 0 ----
    __syncthreads();
    if (threadIdx.x == 0) {
        __threadfence();
        s_last = (atomicAdd(&g_fin, 1) == DEC_BLOCKS - 1) ? 1 : 0;
    }
    __syncthreads();
    if (s_last) {
        float4 z = make_float4(0.f, 0.f, 0.f, 0.f);
#pragma unroll
        for (int p = 0; p < NN * EMB_NF / 4 / 256; p++)     // 16 float4/thread
            reinterpret_cast<float4*>(g_emb)[p * 256 + threadIdx.x] = z;
        if (threadIdx.x == 0) g_fin = 0;
    }
}

// ---------------------------------------------------------------------------
// launch
// ---------------------------------------------------------------------------
extern "C" void kernel_launch(void* const* d_in, const int* in_sizes, int n_in,
                              void* d_out, int out_size) {
    const float* node_feats = (const float*)d_in[0];
    const int*   edge_index = (const int*)d_in[1];
    const float* edge_attr  = (const float*)d_in[2];
    const float* W1 = (const float*)d_in[3];
    const float* b1 = (const float*)d_in[4];
    const float* W2 = (const float*)d_in[5];
    const float* b2 = (const float*)d_in[6];
    const float* We = (const float*)d_in[7];
    const float* be = (const float*)d_in[8];

    float* out = (float*)d_out;
    float* out_emb = out + (size_t)NN * NN;   // adj [N*N] then node_emb [N*2]

    k_fused<<<SCAT_BLK + INIT_BLK, 256>>>(edge_index, edge_attr, node_feats,
                                          W1, b1, W2, b2, We, be);

    // k_decode with programmatic dependent launch (overlap launch ramp with
    // k_fused). Fall back to a plain launch if the attribute is rejected.
    cudaLaunchAttribute attrs[1];
    attrs[0].id = cudaLaunchAttributeProgrammaticStreamSerialization;
    attrs[0].val.programmaticStreamSerializationAllowed = 1;
    cudaLaunchConfig_t cfg = {};
    cfg.gridDim  = dim3(DEC_BLOCKS, 1, 1);
    cfg.blockDim = dim3(256, 1, 1);
    cfg.dynamicSmemBytes = 0;
    cfg.attrs    = attrs;
    cfg.numAttrs = 1;
    cudaError_t err = cudaLaunchKernelEx(&cfg, k_decode, out, out_emb);
    if (err != cudaSuccess) {
        (void)cudaGetLastError();   // clear sticky error, fall back
        k_decode<<<DEC_BLOCKS, 256>>>(out, out_emb);
    }
}